// round 3
// baseline (speedup 1.0000x reference)
#include <cuda_runtime.h>
#include <math.h>

#define BATCH 16
#define HW 256
#define NT (BATCH*HW)   // 4096 total columns

// ---------------- scratch (no allocations allowed) ----------------
__device__ float g_h[BATCH*256*HW];      // conv_in output
__device__ float g_lnp[BATCH*128*HW];    // layernorm out (p)
__device__ float g_lnn[BATCH*128*HW];    // layernorm out (n)
__device__ float g_zp[BATCH*1024*HW];    // z_p (post-silu)
__device__ float g_zn[BATCH*1024*HW];    // z_n
__device__ float g_zqp[BATCH*1024*HW];   // zq_p channel layout
__device__ float g_zqn[BATCH*1024*HW];   // zq_n channel layout
__device__ float g_hcat[BATCH*256*HW];   // concat(hout_p, hout_n)
__device__ float g_cnorm[1024];
__device__ float g_loss_part[1024];      // 512 per branch, deterministic reduction

__device__ __forceinline__ float silu_f(float v){ return v / (1.f + expf(-v)); }

// ---------------- codebook norms (sequential fp32, like ref's reduce) ----------------
__global__ void cnorm_kernel(const float* __restrict__ cb){
  int j = blockIdx.x*blockDim.x + threadIdx.x;
  if (j < 1024){
    float s = 0.f;
    #pragma unroll
    for (int e=0;e<32;e++){ float v = cb[j*32+e]; s = fmaf(v,v,s); }
    g_cnorm[j] = s;
  }
}

// ---------------- generic 1x1-conv GEMM ----------------
// Y[b, oc_off+m, p] = act( bias[m] + sum_k W[m,k] * act_in(X[b, cin_off+k, p]) )
// BM=BN=64, BK=16, 256 threads, 4x4 register tile per thread.
template<bool SILU_IN, bool SILU_OUT>
__global__ void gemm_kernel(const float* __restrict__ W, const float* __restrict__ bias,
                            const float* __restrict__ X, float* __restrict__ Y,
                            int M, int Kd, int CinTot, int cin_off, int OCtot, int oc_off)
{
  __shared__ __align__(16) float As[16][64];
  __shared__ __align__(16) float Bs[16][64];
  const int tid = threadIdx.x;
  const int tx = tid & 15, ty = tid >> 4;
  const int j0 = blockIdx.x * 64;        // column tile (stays inside one batch image)
  const int m0 = blockIdx.y * 64;
  const int b  = j0 >> 8;
  const int p0 = j0 & 255;

  float acc[4][4];
  #pragma unroll
  for (int i=0;i<4;i++)
    #pragma unroll
    for (int j=0;j<4;j++) acc[i][j] = 0.f;

  for (int k0=0;k0<Kd;k0+=16){
    #pragma unroll
    for (int i=0;i<4;i++){
      int e = tid + i*256;
      int m = e >> 4, k = e & 15;
      As[k][m] = W[(m0+m)*Kd + k0 + k];
    }
    #pragma unroll
    for (int i=0;i<4;i++){
      int e = tid + i*256;
      int k = e >> 6, j = e & 63;
      float v = X[((b*CinTot) + cin_off + k0 + k)*HW + p0 + j];
      if (SILU_IN) v = silu_f(v);
      Bs[k][j] = v;
    }
    __syncthreads();
    #pragma unroll
    for (int kk=0;kk<16;kk++){
      float4 a  = *reinterpret_cast<const float4*>(&As[kk][ty*4]);
      float4 bv = *reinterpret_cast<const float4*>(&Bs[kk][tx*4]);
      float av[4] = {a.x,a.y,a.z,a.w};
      float bb[4] = {bv.x,bv.y,bv.z,bv.w};
      #pragma unroll
      for (int i=0;i<4;i++)
        #pragma unroll
        for (int j=0;j<4;j++)
          acc[i][j] = fmaf(av[i], bb[j], acc[i][j]);
    }
    __syncthreads();
  }

  #pragma unroll
  for (int i=0;i<4;i++){
    int m = m0 + ty*4 + i;
    float bb = bias[m];
    #pragma unroll
    for (int j=0;j<4;j++){
      float v = acc[i][j] + bb;
      if (SILU_OUT) v = silu_f(v);
      Y[((b*OCtot) + oc_off + m)*HW + p0 + tx*4 + j] = v;
    }
  }
}

// ---------------- per-sample layernorm over silu(h[:, off:off+128]) ----------------
__global__ void layernorm_kernel(const float* __restrict__ H, int cin_off,
                                 const float* __restrict__ w, const float* __restrict__ bp,
                                 float* __restrict__ out)
{
  const int b = blockIdx.x;
  const float* base = H + (b*256 + cin_off)*HW;   // 32768 contiguous floats
  float s = 0.f, sq = 0.f;
  for (int i=threadIdx.x; i<32768; i+=1024){
    float v = silu_f(base[i]);
    s += v; sq = fmaf(v, v, sq);
  }
  __shared__ float rs[32], rq[32];
  #pragma unroll
  for (int o=16;o>0;o>>=1){
    s  += __shfl_down_sync(0xffffffffu, s,  o);
    sq += __shfl_down_sync(0xffffffffu, sq, o);
  }
  int wid = threadIdx.x >> 5, lid = threadIdx.x & 31;
  if (lid == 0){ rs[wid] = s; rq[wid] = sq; }
  __syncthreads();
  if (wid == 0){
    s = rs[lid]; sq = rq[lid];
    #pragma unroll
    for (int o=16;o>0;o>>=1){
      s  += __shfl_down_sync(0xffffffffu, s,  o);
      sq += __shfl_down_sync(0xffffffffu, sq, o);
    }
    if (lid == 0){ rs[0] = s; rq[0] = sq; }
  }
  __syncthreads();
  float mu   = rs[0] * (1.f/32768.f);
  float var  = rq[0] * (1.f/32768.f) - mu*mu;
  float rstd = rsqrtf(var + 1e-5f);
  float* ob = out + b*32768;
  for (int i=threadIdx.x; i<32768; i+=1024){
    float v = silu_f(base[i]);
    ob[i] = (v - mu) * rstd * w[i] + bp[i];
  }
}

// ---------------- fused VQ: gather vector, argmin over 1024 codes, scatter zq ----------------
// channel index c = e*(LV*KP) + l*KP + kp ; flat vector n = kp*256 + p
// Score reproduces the reference bit-for-bit (modulo zz, which is grid-offset
// invariant):
//   zc = strictly sequential fp32 fma over e=0..31   (Eigen gebp accumulation)
//   t  = fp32(zz - 2*zc); score = fp32(t + cc)       (XLA elementwise tree)
// Ties broken by first index (strict <, ascending j) as in argmin.
template<int KP, int LV, bool WRITE_OUT>
__global__ void quantize_kernel(const float* __restrict__ Z, const float* __restrict__ cb,
                                float* __restrict__ zq_out, float* __restrict__ zq_chan,
                                float* __restrict__ loss_slot)
{
  const int bx = blockIdx.x;
  const int l  = bx % LV;
  const int kp = (bx / LV) % KP;
  const int b  = bx / (LV*KP);
  const int p  = threadIdx.x;

  float z[32];
  float zz = 0.f;
  #pragma unroll
  for (int e=0;e<32;e++){
    float v = Z[((b*1024 + e*(LV*KP) + l*KP + kp)*HW) + p];
    z[e] = v; zz = fmaf(v, v, zz);
  }

  __shared__ __align__(16) float sC[128*32];
  __shared__ float sN[128];
  float best = 3.4e38f; int bestj = 0;

  for (int ch=0; ch<1024; ch+=128){
    for (int i=threadIdx.x; i<4096; i+=256) sC[i] = cb[ch*32 + i];
    if (threadIdx.x < 128) sN[threadIdx.x] = g_cnorm[ch + threadIdx.x];
    __syncthreads();
    // 4 candidates interleaved; each accumulator is a strictly sequential
    // fp32 fma chain over e = 0..31 (matches Eigen's k-sequential gebp).
    for (int jj=0;jj<128;jj+=4){
      const float4* c0 = reinterpret_cast<const float4*>(&sC[(jj+0)*32]);
      const float4* c1 = reinterpret_cast<const float4*>(&sC[(jj+1)*32]);
      const float4* c2 = reinterpret_cast<const float4*>(&sC[(jj+2)*32]);
      const float4* c3 = reinterpret_cast<const float4*>(&sC[(jj+3)*32]);
      float a0=0.f, a1=0.f, a2=0.f, a3=0.f;
      #pragma unroll
      for (int q=0;q<8;q++){
        float4 v0 = c0[q], v1 = c1[q], v2 = c2[q], v3 = c3[q];
        float vv0[4] = {v0.x,v0.y,v0.z,v0.w};
        float vv1[4] = {v1.x,v1.y,v1.z,v1.w};
        float vv2[4] = {v2.x,v2.y,v2.z,v2.w};
        float vv3[4] = {v3.x,v3.y,v3.z,v3.w};
        #pragma unroll
        for (int r=0;r<4;r++){
          float ze = z[4*q+r];
          a0 = fmaf(ze, vv0[r], a0);
          a1 = fmaf(ze, vv1[r], a1);
          a2 = fmaf(ze, vv2[r], a2);
          a3 = fmaf(ze, vv3[r], a3);
        }
      }
      float s0 = (zz - 2.f*a0) + sN[jj+0];
      float s1 = (zz - 2.f*a1) + sN[jj+1];
      float s2 = (zz - 2.f*a2) + sN[jj+2];
      float s3 = (zz - 2.f*a3) + sN[jj+3];
      if (s0 < best){ best = s0; bestj = ch + jj + 0; }
      if (s1 < best){ best = s1; bestj = ch + jj + 1; }
      if (s2 < best){ best = s2; bestj = ch + jj + 2; }
      if (s3 < best){ best = s3; bestj = ch + jj + 3; }
    }
    __syncthreads();
  }

  // loss contribution: best score IS |z - c_best|^2 (to fp32 rounding);
  // deterministic per-block sum
  float s = best;
  #pragma unroll
  for (int o=16;o>0;o>>=1) s += __shfl_down_sync(0xffffffffu, s, o);
  __shared__ float red[8];
  if ((threadIdx.x & 31) == 0) red[threadIdx.x >> 5] = s;
  __syncthreads();
  if (threadIdx.x == 0){
    float t = 0.f;
    #pragma unroll
    for (int i=0;i<8;i++) t += red[i];
    loss_slot[blockIdx.x] = t;
  }

  const float4* cbest = reinterpret_cast<const float4*>(cb + bestj*32);
  #pragma unroll
  for (int q=0;q<8;q++){
    float4 v4 = cbest[q];
    float vv[4] = {v4.x, v4.y, v4.z, v4.w};
    #pragma unroll
    for (int r=0;r<4;r++){
      int e = q*4 + r;
      zq_chan[(b*1024 + e*(LV*KP) + l*KP + kp)*HW + p] = vv[r];
      if (WRITE_OUT)
        zq_out[(((b*32 + e)*(KP*HW)) + kp*HW + p)*LV + l] = vv[r];
    }
  }
}

// ---------------- deterministic loss finalize ----------------
__global__ void loss_final_kernel(float* __restrict__ out_loss){
  __shared__ float red[256];
  float s = 0.f;
  for (int i=threadIdx.x; i<1024; i+=256) s += g_loss_part[i];
  red[threadIdx.x] = s;
  __syncthreads();
  for (int o=128;o>0;o>>=1){
    if (threadIdx.x < o) red[threadIdx.x] += red[threadIdx.x + o];
    __syncthreads();
  }
  if (threadIdx.x == 0)
    *out_loss = 1.25f * red[0] / 4194304.f;   // beta=0.25 -> (1+0.25)*mean, both branches /(B*N*L*E)=4194304
}

// ---------------- launch ----------------
extern "C" void kernel_launch(void* const* d_in, const int* in_sizes, int n_in,
                              void* d_out, int out_size)
{
  const float* x          = (const float*)d_in[0];
  const float* conv_in_w  = (const float*)d_in[1];
  const float* conv_in_b  = (const float*)d_in[2];
  const float* ln_p_w     = (const float*)d_in[3];
  const float* ln_p_b     = (const float*)d_in[4];
  const float* wp_in      = (const float*)d_in[5];
  const float* bp_in      = (const float*)d_in[6];
  const float* wp_out     = (const float*)d_in[7];
  const float* bp_out     = (const float*)d_in[8];
  const float* ln_n_w     = (const float*)d_in[9];
  const float* ln_n_b     = (const float*)d_in[10];
  const float* wn_in      = (const float*)d_in[11];
  const float* bn_in      = (const float*)d_in[12];
  const float* wn_out     = (const float*)d_in[13];
  const float* bn_out     = (const float*)d_in[14];
  const float* codebook   = (const float*)d_in[15];
  const float* conv_out_w = (const float*)d_in[16];
  const float* conv_out_b = (const float*)d_in[17];

  float* out      = (float*)d_out;               // [16,256,16,16]
  float* out_loss = out + 1048576;               // scalar
  float* out_zq   = out + 1048577;               // [16,32,2048,4]

  float *hbuf,*lnp,*lnn,*zp,*zn,*zqp,*zqn,*hcat,*lpart;
  cudaGetSymbolAddress((void**)&hbuf,  g_h);
  cudaGetSymbolAddress((void**)&lnp,   g_lnp);
  cudaGetSymbolAddress((void**)&lnn,   g_lnn);
  cudaGetSymbolAddress((void**)&zp,    g_zp);
  cudaGetSymbolAddress((void**)&zn,    g_zn);
  cudaGetSymbolAddress((void**)&zqp,   g_zqp);
  cudaGetSymbolAddress((void**)&zqn,   g_zqn);
  cudaGetSymbolAddress((void**)&hcat,  g_hcat);
  cudaGetSymbolAddress((void**)&lpart, g_loss_part);

  // codebook norms (independent of everything downstream of conv_in)
  cnorm_kernel<<<4, 256>>>(codebook);

  // h = conv_in(silu(x))
  gemm_kernel<true,false><<<dim3(NT/64, 256/64), 256>>>(
      conv_in_w, conv_in_b, x, hbuf, 256, 256, 256, 0, 256, 0);

  // layernorms over silu(h_p), silu(h_n)
  layernorm_kernel<<<BATCH, 1024>>>(hbuf, 0,   ln_p_w, ln_p_b, lnp);
  layernorm_kernel<<<BATCH, 1024>>>(hbuf, 128, ln_n_w, ln_n_b, lnn);

  // z = silu(W_in @ ln + b)
  gemm_kernel<false,true><<<dim3(NT/64, 1024/64), 256>>>(
      wp_in, bp_in, lnp, zp, 1024, 128, 128, 0, 1024, 0);
  gemm_kernel<false,true><<<dim3(NT/64, 1024/64), 256>>>(
      wn_in, bn_in, lnn, zn, 1024, 128, 128, 0, 1024, 0);

  // VQ: p branch (Kp=8, L=4, writes zq_p output), n branch (Kp=32, L=1)
  quantize_kernel<8,4,true><<<BATCH*8*4, 256>>>(zp, codebook, out_zq, zqp, lpart);
  quantize_kernel<32,1,false><<<BATCH*32*1, 256>>>(zn, codebook, nullptr, zqn, lpart + 512);

  // hout = silu(W_out @ zq + b), written into concat buffer
  gemm_kernel<false,true><<<dim3(NT/64, 128/64), 256>>>(
      wp_out, bp_out, zqp, hcat, 128, 1024, 1024, 0, 256, 0);
  gemm_kernel<false,true><<<dim3(NT/64, 128/64), 256>>>(
      wn_out, bn_out, zqn, hcat, 128, 1024, 1024, 0, 256, 128);

  // out = conv_out(silu(h_cat))
  gemm_kernel<true,false><<<dim3(NT/64, 256/64), 256>>>(
      conv_out_w, conv_out_b, hcat, out, 256, 256, 256, 0, 256, 0);

  // deterministic loss reduction
  loss_final_kernel<<<1, 256>>>(out_loss);
}